// round 15
// baseline (speedup 1.0000x reference)
#include <cuda_runtime.h>
#include <cuda_fp16.h>
#include <math_constants.h>

#define NN   50000
#define EE   1600000
#define ETOT 1650000      // EE + NN self loops
#define INCH 34
#define H1   2
#define F1   128          // layer1 concat width
#define F2   64           // layer2 out width
#define NEG  0.2f
#define NBLK ((NN + 255) / 256)     // 196 scan blocks
#define EB   ((ETOT + 255) / 256)   // 6446 edge blocks
#define NB64 ((NN + 63) / 64)       // 782 k1 tile-pair blocks

struct __align__(8)  half4 { __half2 lo, hi; };
struct __align__(16) Edge1 { int src; float w0, w1; int pad; };

// ---- scratch (static device globals; zero-initialized at load; self-cleaning) ----
__device__ __half g_xw1h[NN * F1];   // x @ W1 (fp16 storage)      [N,128]
__device__ __half g_xw2h[NN * F2];   // relu(h+b1) @ W2 (fp16)     [N,64]
__device__ float  g_hacc[NN * F1];   // layer1 aggregation (fp32)  [N,128]
__device__ float  g_al1s[NN * H1];
__device__ float  g_al1d[NN * H1];
__device__ float  g_al2s[NN];
__device__ float  g_al2d[NN];
__device__ int    g_cnt [NN];        // dst histogram (zeroed by kscatter for next call)
__device__ int    g_off [NN + 1];    // CSR offsets
__device__ unsigned int g_desc[NBLK];// lookback descriptors (zeroed by kscatter)
__device__ int    g_rank[ETOT];      // rank of edge within its dst bucket
__device__ Edge1  g_e1  [ETOT];      // bucketed edge records: src + both head weights
__device__ int    g_esrc[ETOT];      // src index per edge, bucketed (for kagg2)

__device__ __forceinline__ float lrelu(float v){ return v >= 0.f ? v : NEG * v; }

// per-block dtype probe: node ids < NN as int64 iff buffer is int64
__device__ __forceinline__ bool detect_is64(const void* __restrict__ ei, int* sflag){
    if (threadIdx.x < 32){
        const long long* p = (const long long*)ei;
        int lane = threadIdx.x;
        bool bad = (p[lane] < 0) || (p[lane] >= NN) ||
                   (p[lane + 32] < 0) || (p[lane + 32] >= NN);
        unsigned anybad = __ballot_sync(0xffffffffu, bad);
        if (lane == 0) *sflag = anybad ? 0 : 1;
    }
    __syncthreads();
    return *sflag != 0;
}

__device__ __forceinline__ void edge_sd(const void* __restrict__ ei, bool is64,
                                        int e, int& s, int& d){
    if (e < EE){
        if (is64){
            const long long* p = (const long long*)ei;
            s = (int)p[e]; d = (int)p[EE + e];
        } else {
            const int* p = (const int*)ei;
            s = p[e]; d = p[EE + e];
        }
    } else {
        s = e - EE; d = s;
    }
}

// ---------------- fused: histogram+rank (blocks 0..EB) | k1 projection+logits (rest) ----------------
__global__ void kfused(const void* __restrict__ ei,
                       const float* __restrict__ x, const float* __restrict__ W1,
                       const float* __restrict__ as1, const float* __restrict__ ad1){
    __shared__ float sx[2][32][36];
    __shared__ float sxw[2][32][F1];
    __shared__ int   sflag;
    int bid = blockIdx.x;

    if (bid < EB){                                  // -------- histogram + rank --------
        bool is64 = detect_is64(ei, &sflag);
        int e = bid * 256 + threadIdx.x;
        if (e < ETOT){
            int s, d; edge_sd(ei, is64, e, s, d);
            g_rank[e] = atomicAdd(&g_cnt[d], 1);
        }
        return;
    }

    // ---------------- k1: two 32-node tiles per block ----------------
    int bk  = bid - EB;
    int sub = threadIdx.x >> 7;                     // 0 or 1: which tile
    int t   = threadIdx.x & 127;                    // channel within tile
    int n0  = bk * 64 + sub * 32;
    int nn  = NN - n0; nn = nn < 0 ? 0 : (nn > 32 ? 32 : nn);
    float (*px)[36] = sx[sub];
    float (*pw)[F1] = sxw[sub];

    int tot = nn * INCH;
    for (int i = t; i < tot; i += 128){
        int r = i / INCH, c = i - r * INCH;
        px[r][c] = x[n0 * INCH + i];
    }
    if (t < 32){ px[t][34] = 0.f; px[t][35] = 0.f; }

    float w[36];
    #pragma unroll
    for (int k = 0; k < INCH; k++) w[k] = W1[k * F1 + t];
    w[34] = 0.f; w[35] = 0.f;
    __syncthreads();

    int n = 0;
    for (; n + 2 <= nn; n += 2){                    // 2-node unroll
        float a0 = 0.f, a1 = 0.f, c0 = 0.f, c1 = 0.f;
        #pragma unroll
        for (int k4 = 0; k4 < 9; k4++){
            float4 b = *reinterpret_cast<const float4*>(&px[n][k4 * 4]);
            float4 d = *reinterpret_cast<const float4*>(&px[n + 1][k4 * 4]);
            a0 = fmaf(b.x, w[k4*4],   a0);
            a1 = fmaf(b.y, w[k4*4+1], a1);
            a0 = fmaf(b.z, w[k4*4+2], a0);
            a1 = fmaf(b.w, w[k4*4+3], a1);
            c0 = fmaf(d.x, w[k4*4],   c0);
            c1 = fmaf(d.y, w[k4*4+1], c1);
            c0 = fmaf(d.z, w[k4*4+2], c0);
            c1 = fmaf(d.w, w[k4*4+3], c1);
        }
        float r0 = a0 + a1, r1 = c0 + c1;
        pw[n][t] = r0;      g_xw1h[(n0 + n) * F1 + t]     = __float2half_rn(r0);
        pw[n + 1][t] = r1;  g_xw1h[(n0 + n + 1) * F1 + t] = __float2half_rn(r1);
    }
    for (; n < nn; n++){
        float a0 = 0.f, a1 = 0.f;
        #pragma unroll
        for (int k4 = 0; k4 < 9; k4++){
            float4 b = *reinterpret_cast<const float4*>(&px[n][k4 * 4]);
            a0 = fmaf(b.x, w[k4*4],   a0);
            a1 = fmaf(b.y, w[k4*4+1], a1);
            a0 = fmaf(b.z, w[k4*4+2], a0);
            a1 = fmaf(b.w, w[k4*4+3], a1);
        }
        float acc = a0 + a1;
        pw[n][t] = acc;
        g_xw1h[(n0 + n) * F1 + t] = __float2half_rn(acc);
    }
    __syncthreads();

    // fused logits: each of 4 warps (per tile) reduces 8 nodes
    int wid = t >> 5, lane = t & 31, h = lane >> 4;
    float4 av = *reinterpret_cast<const float4*>(as1 + lane * 4);
    float4 dv = *reinterpret_cast<const float4*>(ad1 + lane * 4);
    int nend = wid * 8 + 8; if (nend > nn) nend = nn;
    for (int m = wid * 8; m < nend; m++){
        float4 v = *reinterpret_cast<const float4*>(&pw[m][lane * 4]);
        float vs = v.x * av.x + v.y * av.y + v.z * av.z + v.w * av.w;
        float vd = v.x * dv.x + v.y * dv.y + v.z * dv.z + v.w * dv.w;
        #pragma unroll
        for (int off = 8; off; off >>= 1){
            vs += __shfl_xor_sync(0xffffffffu, vs, off);
            vd += __shfl_xor_sync(0xffffffffu, vd, off);
        }
        if ((lane & 15) == 0){
            g_al1s[(n0 + m) * 2 + h] = vs;
            g_al1d[(n0 + m) * 2 + h] = vd;
        }
    }
}

// ---------------- single-pass decoupled-lookback scan ----------------
__global__ void kscan(){
    __shared__ int s[256];
    __shared__ int sbase;
    int b = blockIdx.x, t = threadIdx.x;
    int idx = b * 256 + t;
    int v = (idx < NN) ? g_cnt[idx] : 0;
    s[t] = v;
    __syncthreads();
    #pragma unroll
    for (int off = 1; off < 256; off <<= 1){
        int u = (t >= off) ? s[t - off] : 0;
        __syncthreads();
        s[t] += u;
        __syncthreads();
    }
    int incl = s[t];
    int agg  = s[255];
    if (t == 0){
        if (b == 0){
            sbase = 0;
            atomicExch(&g_desc[0], 0x80000000u | (unsigned)agg);   // PREFIX
        } else {
            atomicExch(&g_desc[b], 0x40000000u | (unsigned)agg);   // AGGREGATE
            int sum = 0;
            for (int p = b - 1; p >= 0; ){
                unsigned d;
                do { d = atomicAdd(&g_desc[p], 0u); } while (d == 0u);
                sum += (int)(d & 0x3FFFFFFFu);
                if (d & 0x80000000u) break;
                p--;
            }
            sbase = sum;
            atomicExch(&g_desc[b], 0x80000000u | (unsigned)(sum + agg));
        }
    }
    __syncthreads();
    if (idx < NN) g_off[idx] = sbase + incl - v;
    if (b == NBLK - 1 && t == 255) g_off[NN] = ETOT;
}

// ---------------- scatter: one 16B edge record per edge + cleanup ----------------
__global__ void kscatter(const void* __restrict__ ei){
    __shared__ int sflag;
    bool is64 = detect_is64(ei, &sflag);
    int e = blockIdx.x * blockDim.x + threadIdx.x;
    if (e < ETOT){
        int s, d; edge_sd(ei, is64, e, s, d);
        int pos = g_off[d] + g_rank[e];
        float2 als = *reinterpret_cast<const float2*>(g_al1s + s * 2);
        float2 ald = *reinterpret_cast<const float2*>(g_al1d + d * 2);
        Edge1 rec;
        rec.src = s;
        rec.w0  = __expf(lrelu(als.x + ald.x));
        rec.w1  = __expf(lrelu(als.y + ald.y));
        rec.pad = 0;
        g_e1[pos]   = rec;      // single scattered STG.128 (1 sector/edge)
        g_esrc[pos] = s;        // for kagg2 (uniform-read path)
    }
    if (e < NN)   g_cnt[e]  = 0;      // ready for next call
    if (e < NBLK) g_desc[e] = 0u;
}

// ---------------- layer1 aggregation: edge-record loop (no expf, no staging) ----------------
__global__ void kagg1(){
    int wid  = threadIdx.x >> 5;
    int lane = threadIdx.x & 31;
    int w    = blockIdx.x * 8 + wid;
    if (w >= NN) return;
    int beg = g_off[w], end = g_off[w + 1];
    int h   = lane >> 4;                           // lanes 0-15 head0, 16-31 head1
    const __half* base = g_xw1h + lane * 4;        // lane owns 4 of 128 channels

    float den = 0.f;
    float a0 = 0.f, a1 = 0.f, a2 = 0.f, a3 = 0.f;
    int j = beg;
    for (; j + 4 <= end; j += 4){
        Edge1 e0 = g_e1[j],   e1 = g_e1[j+1];      // uniform LDG.128 broadcasts
        Edge1 e2 = g_e1[j+2], e3 = g_e1[j+3];
        float w0 = h ? e0.w1 : e0.w0;
        float w1 = h ? e1.w1 : e1.w0;
        float w2 = h ? e2.w1 : e2.w0;
        float w3 = h ? e3.w1 : e3.w0;
        half4 u0 = *reinterpret_cast<const half4*>(base + e0.src * F1);
        half4 u1 = *reinterpret_cast<const half4*>(base + e1.src * F1);
        half4 u2 = *reinterpret_cast<const half4*>(base + e2.src * F1);
        half4 u3 = *reinterpret_cast<const half4*>(base + e3.src * F1);
        den += (w0 + w1) + (w2 + w3);
        float2 p, q;
        p = __half22float2(u0.lo); q = __half22float2(u0.hi);
        a0 = fmaf(p.x, w0, a0); a1 = fmaf(p.y, w0, a1); a2 = fmaf(q.x, w0, a2); a3 = fmaf(q.y, w0, a3);
        p = __half22float2(u1.lo); q = __half22float2(u1.hi);
        a0 = fmaf(p.x, w1, a0); a1 = fmaf(p.y, w1, a1); a2 = fmaf(q.x, w1, a2); a3 = fmaf(q.y, w1, a3);
        p = __half22float2(u2.lo); q = __half22float2(u2.hi);
        a0 = fmaf(p.x, w2, a0); a1 = fmaf(p.y, w2, a1); a2 = fmaf(q.x, w2, a2); a3 = fmaf(q.y, w2, a3);
        p = __half22float2(u3.lo); q = __half22float2(u3.hi);
        a0 = fmaf(p.x, w3, a0); a1 = fmaf(p.y, w3, a1); a2 = fmaf(q.x, w3, a2); a3 = fmaf(q.y, w3, a3);
    }
    for (; j < end; j++){
        Edge1 e  = g_e1[j];
        float ww = h ? e.w1 : e.w0;
        half4 u  = *reinterpret_cast<const half4*>(base + e.src * F1);
        float2 p = __half22float2(u.lo), q = __half22float2(u.hi);
        den += ww;
        a0 = fmaf(p.x, ww, a0); a1 = fmaf(p.y, ww, a1);
        a2 = fmaf(q.x, ww, a2); a3 = fmaf(q.y, ww, a3);
    }
    float r = 1.f / den;
    *reinterpret_cast<float4*>(g_hacc + w * F1 + lane * 4) =
        make_float4(a0 * r, a1 * r, a2 * r, a3 * r);
}

// ---------------- layer2 projection + fused logits ----------------
__global__ void k5(const float* __restrict__ b1, const float* __restrict__ W2,
                   const float* __restrict__ as2, const float* __restrict__ ad2){
    __shared__ float sh[32][F1];                   // 16 KB
    __shared__ float so[32][F2];                   // 8 KB
    int n0 = blockIdx.x * 32;
    int t  = threadIdx.x;                          // 128 threads
    int nn = min(32, NN - n0);

    float bb = b1[t];
    for (int r = 0; r < nn; r++)
        sh[r][t] = fmaxf(g_hacc[(n0 + r) * F1 + t] + bb, 0.f);
    __syncthreads();

    int c = t & 63, g = t >> 6;                    // channel, node-parity
    float acc[16];
    #pragma unroll
    for (int m = 0; m < 16; m++) acc[m] = 0.f;

    #pragma unroll
    for (int q = 0; q < 4; q++){
        float wreg[32];
        #pragma unroll
        for (int kk = 0; kk < 32; kk++) wreg[kk] = W2[(q * 32 + kk) * F2 + c];
        #pragma unroll 4
        for (int m = 0; m < 16; m++){
            int n = 2 * m + g;
            float a = acc[m];
            #pragma unroll
            for (int k4 = 0; k4 < 8; k4++){
                float4 b = *reinterpret_cast<const float4*>(&sh[n][q * 32 + k4 * 4]);
                a = fmaf(b.x, wreg[k4*4],   a);
                a = fmaf(b.y, wreg[k4*4+1], a);
                a = fmaf(b.z, wreg[k4*4+2], a);
                a = fmaf(b.w, wreg[k4*4+3], a);
            }
            acc[m] = a;
        }
    }
    #pragma unroll
    for (int m = 0; m < 16; m++){
        int n = 2 * m + g;
        if (n < nn){
            so[n][c] = acc[m];
            g_xw2h[(n0 + n) * F2 + c] = __float2half_rn(acc[m]);
        }
    }
    __syncthreads();

    int wid = t >> 5, lane = t & 31;
    float2 av = *reinterpret_cast<const float2*>(as2 + lane * 2);
    float2 dv = *reinterpret_cast<const float2*>(ad2 + lane * 2);
    int nend = min(wid * 8 + 8, nn);
    for (int n = wid * 8; n < nend; n++){
        float2 v = *reinterpret_cast<const float2*>(&so[n][lane * 2]);
        float vs = v.x * av.x + v.y * av.y;
        float vd = v.x * dv.x + v.y * dv.y;
        #pragma unroll
        for (int off = 16; off; off >>= 1){
            vs += __shfl_xor_sync(0xffffffffu, vs, off);
            vd += __shfl_xor_sync(0xffffffffu, vd, off);
        }
        if (lane == 0){ g_al2s[n0 + n] = vs; g_al2d[n0 + n] = vd; }
    }
}

// ---------------- layer2 aggregation: smem-staged cooperative weights ----------------
__global__ void kagg2(float* __restrict__ out, const float* __restrict__ b2){
    __shared__ float swt[8][16];                   // per-warp: 16 edge weights
    int wid  = threadIdx.x >> 5;
    int lane = threadIdx.x & 31;
    int w    = blockIdx.x * 8 + wid;
    if (w >= NN) return;
    int beg = g_off[w], end = g_off[w + 1];
    float ald = g_al2d[w];
    const __half2* xwc = reinterpret_cast<const __half2*>(g_xw2h) + lane;
    const int ROW2 = F2 / 2;

    float den = 0.f, a0 = 0.f, a1 = 0.f;
    int j = beg;
    for (; j + 16 <= end; j += 16){
        if (lane < 16){
            int myidx = g_esrc[j + lane];
            swt[wid][lane] = __expf(lrelu(g_al2s[myidx] + ald));
        }
        __syncwarp();
        #pragma unroll
        for (int k = 0; k < 16; k++){
            int   s  = g_esrc[j + k];
            float wk = swt[wid][k];
            float2 v = __half22float2(xwc[s * ROW2]);
            den += wk;
            a0 = fmaf(v.x, wk, a0); a1 = fmaf(v.y, wk, a1);
        }
        __syncwarp();
    }
    for (; j < end; j++){
        int   s  = g_esrc[j];
        float ww = __expf(lrelu(g_al2s[s] + ald));
        float2 v = __half22float2(xwc[s * ROW2]);
        den += ww;
        a0 = fmaf(v.x, ww, a0); a1 = fmaf(v.y, ww, a1);
    }
    float r = 1.f / den;
    *reinterpret_cast<float2*>(out + w * F2 + lane * 2) =
        make_float2(fmaf(a0, r, __ldg(b2 + lane * 2)),
                    fmaf(a1, r, __ldg(b2 + lane * 2 + 1)));
}

extern "C" void kernel_launch(void* const* d_in, const int* in_sizes, int n_in,
                              void* d_out, int out_size){
    const float* x   = (const float*)d_in[0];
    const void*  ei  = d_in[1];
    const float* W1  = (const float*)d_in[2];
    const float* as1 = (const float*)d_in[3];
    const float* ad1 = (const float*)d_in[4];
    const float* b1  = (const float*)d_in[5];
    const float* W2  = (const float*)d_in[6];
    const float* as2 = (const float*)d_in[7];
    const float* ad2 = (const float*)d_in[8];
    const float* b2  = (const float*)d_in[9];
    float* out = (float*)d_out;

    int wb = (NN + 7) / 8;                          // 8 warps per block
    int nb = (NN + 31) / 32;

    kfused<<<EB + NB64, 256>>>(ei, x, W1, as1, ad1);   // histogram+rank | k1
    kscan<<<NBLK, 256>>>();
    kscatter<<<EB, 256>>>(ei);                          // 16B edge records
    kagg1<<<wb, 256>>>();                               // launch #4 → profiled
    k5<<<nb, 128>>>(b1, W2, as2, ad2);
    kagg2<<<wb, 256>>>(out, b2);
}

// round 16
// speedup vs baseline: 1.0623x; 1.0623x over previous
#include <cuda_runtime.h>
#include <cuda_fp16.h>
#include <math_constants.h>

#define NN   50000
#define EE   1600000
#define ETOT 1650000      // EE + NN self loops
#define INCH 34
#define H1   2
#define F1   128          // layer1 concat width
#define F2   64           // layer2 out width
#define NEG  0.2f
#define NBLK ((NN + 255) / 256)     // 196 scan blocks
#define EB   ((ETOT + 255) / 256)   // 6446 edge blocks
#define NB64 ((NN + 63) / 64)       // 782 k1 tile-pair blocks

struct __align__(8) half4 { __half2 lo, hi; };

// ---- scratch (static device globals; zero-initialized at load; self-cleaning) ----
__device__ __half g_xw1h[NN * F1];   // x @ W1 (fp16 storage)      [N,128]
__device__ __half g_xw2h[NN * F2];   // relu(h+b1) @ W2 (fp16)     [N,64]
__device__ float  g_hacc[NN * F1];   // layer1 aggregation (fp32)  [N,128]
__device__ float  g_al1s[NN * H1];
__device__ float  g_al1d[NN * H1];
__device__ float  g_al2s[NN];
__device__ float  g_al2d[NN];
__device__ int    g_cnt [NN];        // dst histogram (zeroed by kscatter for next call)
__device__ int    g_off [NN + 1];    // CSR offsets
__device__ unsigned int g_desc[NBLK];// lookback descriptors (zeroed by kscatter)
__device__ int    g_rank[ETOT];      // rank of edge within its dst bucket
__device__ int    g_esrc[ETOT];      // src index per edge, bucketed by dst

__device__ __forceinline__ float lrelu(float v){ return v >= 0.f ? v : NEG * v; }

// per-block dtype probe: node ids < NN as int64 iff buffer is int64
__device__ __forceinline__ bool detect_is64(const void* __restrict__ ei, int* sflag){
    if (threadIdx.x < 32){
        const long long* p = (const long long*)ei;
        int lane = threadIdx.x;
        bool bad = (p[lane] < 0) || (p[lane] >= NN) ||
                   (p[lane + 32] < 0) || (p[lane + 32] >= NN);
        unsigned anybad = __ballot_sync(0xffffffffu, bad);
        if (lane == 0) *sflag = anybad ? 0 : 1;
    }
    __syncthreads();
    return *sflag != 0;
}

__device__ __forceinline__ void edge_sd(const void* __restrict__ ei, bool is64,
                                        int e, int& s, int& d){
    if (e < EE){
        if (is64){
            const long long* p = (const long long*)ei;
            s = (int)p[e]; d = (int)p[EE + e];
        } else {
            const int* p = (const int*)ei;
            s = p[e]; d = p[EE + e];
        }
    } else {
        s = e - EE; d = s;
    }
}

// ---------------- fused: histogram+rank (blocks 0..EB) | k1 projection+logits (rest) ----------------
__global__ void kfused(const void* __restrict__ ei,
                       const float* __restrict__ x, const float* __restrict__ W1,
                       const float* __restrict__ as1, const float* __restrict__ ad1){
    __shared__ float sx[2][32][36];
    __shared__ float sxw[2][32][F1];
    __shared__ int   sflag;
    int bid = blockIdx.x;

    if (bid < EB){                                  // -------- histogram + rank --------
        bool is64 = detect_is64(ei, &sflag);
        int e = bid * 256 + threadIdx.x;
        if (e < ETOT){
            int s, d; edge_sd(ei, is64, e, s, d);
            g_rank[e] = atomicAdd(&g_cnt[d], 1);
        }
        return;
    }

    // ---------------- k1: two 32-node tiles per block ----------------
    int bk  = bid - EB;
    int sub = threadIdx.x >> 7;                     // 0 or 1: which tile
    int t   = threadIdx.x & 127;                    // channel within tile
    int n0  = bk * 64 + sub * 32;
    int nn  = NN - n0; nn = nn < 0 ? 0 : (nn > 32 ? 32 : nn);
    float (*px)[36] = sx[sub];
    float (*pw)[F1] = sxw[sub];

    int tot = nn * INCH;
    for (int i = t; i < tot; i += 128){
        int r = i / INCH, c = i - r * INCH;
        px[r][c] = x[n0 * INCH + i];
    }
    if (t < 32){ px[t][34] = 0.f; px[t][35] = 0.f; }

    float w[36];
    #pragma unroll
    for (int k = 0; k < INCH; k++) w[k] = W1[k * F1 + t];
    w[34] = 0.f; w[35] = 0.f;
    __syncthreads();

    int n = 0;
    for (; n + 2 <= nn; n += 2){                    // 2-node unroll
        float a0 = 0.f, a1 = 0.f, c0 = 0.f, c1 = 0.f;
        #pragma unroll
        for (int k4 = 0; k4 < 9; k4++){
            float4 b = *reinterpret_cast<const float4*>(&px[n][k4 * 4]);
            float4 d = *reinterpret_cast<const float4*>(&px[n + 1][k4 * 4]);
            a0 = fmaf(b.x, w[k4*4],   a0);
            a1 = fmaf(b.y, w[k4*4+1], a1);
            a0 = fmaf(b.z, w[k4*4+2], a0);
            a1 = fmaf(b.w, w[k4*4+3], a1);
            c0 = fmaf(d.x, w[k4*4],   c0);
            c1 = fmaf(d.y, w[k4*4+1], c1);
            c0 = fmaf(d.z, w[k4*4+2], c0);
            c1 = fmaf(d.w, w[k4*4+3], c1);
        }
        float r0 = a0 + a1, r1 = c0 + c1;
        pw[n][t] = r0;      g_xw1h[(n0 + n) * F1 + t]     = __float2half_rn(r0);
        pw[n + 1][t] = r1;  g_xw1h[(n0 + n + 1) * F1 + t] = __float2half_rn(r1);
    }
    for (; n < nn; n++){
        float a0 = 0.f, a1 = 0.f;
        #pragma unroll
        for (int k4 = 0; k4 < 9; k4++){
            float4 b = *reinterpret_cast<const float4*>(&px[n][k4 * 4]);
            a0 = fmaf(b.x, w[k4*4],   a0);
            a1 = fmaf(b.y, w[k4*4+1], a1);
            a0 = fmaf(b.z, w[k4*4+2], a0);
            a1 = fmaf(b.w, w[k4*4+3], a1);
        }
        float acc = a0 + a1;
        pw[n][t] = acc;
        g_xw1h[(n0 + n) * F1 + t] = __float2half_rn(acc);
    }
    __syncthreads();

    // fused logits: each of 4 warps (per tile) reduces 8 nodes
    int wid = t >> 5, lane = t & 31, h = lane >> 4;
    float4 av = *reinterpret_cast<const float4*>(as1 + lane * 4);
    float4 dv = *reinterpret_cast<const float4*>(ad1 + lane * 4);
    int nend = wid * 8 + 8; if (nend > nn) nend = nn;
    for (int m = wid * 8; m < nend; m++){
        float4 v = *reinterpret_cast<const float4*>(&pw[m][lane * 4]);
        float vs = v.x * av.x + v.y * av.y + v.z * av.z + v.w * av.w;
        float vd = v.x * dv.x + v.y * dv.y + v.z * dv.z + v.w * dv.w;
        #pragma unroll
        for (int off = 8; off; off >>= 1){
            vs += __shfl_xor_sync(0xffffffffu, vs, off);
            vd += __shfl_xor_sync(0xffffffffu, vd, off);
        }
        if ((lane & 15) == 0){
            g_al1s[(n0 + m) * 2 + h] = vs;
            g_al1d[(n0 + m) * 2 + h] = vd;
        }
    }
}

// ---------------- single-pass decoupled-lookback scan ----------------
__global__ void kscan(){
    __shared__ int s[256];
    __shared__ int sbase;
    int b = blockIdx.x, t = threadIdx.x;
    int idx = b * 256 + t;
    int v = (idx < NN) ? g_cnt[idx] : 0;
    s[t] = v;
    __syncthreads();
    #pragma unroll
    for (int off = 1; off < 256; off <<= 1){
        int u = (t >= off) ? s[t - off] : 0;
        __syncthreads();
        s[t] += u;
        __syncthreads();
    }
    int incl = s[t];
    int agg  = s[255];
    if (t == 0){
        if (b == 0){
            sbase = 0;
            atomicExch(&g_desc[0], 0x80000000u | (unsigned)agg);   // PREFIX
        } else {
            atomicExch(&g_desc[b], 0x40000000u | (unsigned)agg);   // AGGREGATE
            int sum = 0;
            for (int p = b - 1; p >= 0; ){
                unsigned d;
                do { d = atomicAdd(&g_desc[p], 0u); } while (d == 0u);
                sum += (int)(d & 0x3FFFFFFFu);
                if (d & 0x80000000u) break;
                p--;
            }
            sbase = sum;
            atomicExch(&g_desc[b], 0x80000000u | (unsigned)(sum + agg));
        }
    }
    __syncthreads();
    if (idx < NN) g_off[idx] = sbase + incl - v;
    if (b == NBLK - 1 && t == 255) g_off[NN] = ETOT;
}

// ---------------- scatter (atomic-free) + state cleanup for next call ----------------
__global__ void kscatter(const void* __restrict__ ei){
    __shared__ int sflag;
    bool is64 = detect_is64(ei, &sflag);
    int e = blockIdx.x * blockDim.x + threadIdx.x;
    if (e < ETOT){
        int s, d; edge_sd(ei, is64, e, s, d);
        g_esrc[g_off[d] + g_rank[e]] = s;
    }
    if (e < NN)   g_cnt[e]  = 0;      // ready for next call
    if (e < NBLK) g_desc[e] = 0u;
}

// ---------------- layer1 aggregation: JIT shuffle-broadcast weights, lean loop ----------------
__global__ void kagg1(){
    int wid  = threadIdx.x >> 5;
    int lane = threadIdx.x & 31;
    int w    = blockIdx.x * 8 + wid;
    if (w >= NN) return;
    int beg = g_off[w], end = g_off[w + 1];
    int h   = lane >> 4;                           // lanes 0-15 head0, 16-31 head1
    float ald = g_al1d[w * 2 + h];
    const __half* base = g_xw1h + lane * 4;        // lane owns 4 of 128 channels
    int srcsel = (lane & 16);                      // shuffle source base for my head

    float den = 0.f;
    float a0 = 0.f, a1 = 0.f, a2 = 0.f, a3 = 0.f;
    int j = beg;
    for (; j + 16 <= end; j += 16){
        // lane (k, k+16) computes weight of edge k for head (0, 1)
        int   myidx = g_esrc[j + (lane & 15)];
        float wmy   = __expf(lrelu(g_al1s[myidx * 2 + h] + ald));
        #pragma unroll
        for (int k = 0; k < 16; k++){
            int   s  = g_esrc[j + k];              // uniform LDG (L1 broadcast)
            float wk = __shfl_sync(0xffffffffu, wmy, srcsel + k);
            half4 u  = *reinterpret_cast<const half4*>(base + s * F1);
            float2 p = __half22float2(u.lo), q = __half22float2(u.hi);
            den += wk;
            a0 = fmaf(p.x, wk, a0); a1 = fmaf(p.y, wk, a1);
            a2 = fmaf(q.x, wk, a2); a3 = fmaf(q.y, wk, a3);
        }
    }
    for (; j < end; j++){
        int   s  = g_esrc[j];
        float ww = __expf(lrelu(g_al1s[s * 2 + h] + ald));
        half4 u  = *reinterpret_cast<const half4*>(base + s * F1);
        float2 p = __half22float2(u.lo), q = __half22float2(u.hi);
        den += ww;
        a0 = fmaf(p.x, ww, a0); a1 = fmaf(p.y, ww, a1);
        a2 = fmaf(q.x, ww, a2); a3 = fmaf(q.y, ww, a3);
    }
    float r = 1.f / den;
    *reinterpret_cast<float4*>(g_hacc + w * F1 + lane * 4) =
        make_float4(a0 * r, a1 * r, a2 * r, a3 * r);
}

// ---------------- layer2 projection + fused logits ----------------
__global__ void k5(const float* __restrict__ b1, const float* __restrict__ W2,
                   const float* __restrict__ as2, const float* __restrict__ ad2){
    __shared__ float sh[32][F1];                   // 16 KB
    __shared__ float so[32][F2];                   // 8 KB
    int n0 = blockIdx.x * 32;
    int t  = threadIdx.x;                          // 128 threads
    int nn = min(32, NN - n0);

    float bb = b1[t];
    for (int r = 0; r < nn; r++)
        sh[r][t] = fmaxf(g_hacc[(n0 + r) * F1 + t] + bb, 0.f);
    __syncthreads();

    int c = t & 63, g = t >> 6;                    // channel, node-parity
    float acc[16];
    #pragma unroll
    for (int m = 0; m < 16; m++) acc[m] = 0.f;

    #pragma unroll
    for (int q = 0; q < 4; q++){
        float wreg[32];
        #pragma unroll
        for (int kk = 0; kk < 32; kk++) wreg[kk] = W2[(q * 32 + kk) * F2 + c];
        #pragma unroll 4
        for (int m = 0; m < 16; m++){
            int n = 2 * m + g;
            float a = acc[m];
            #pragma unroll
            for (int k4 = 0; k4 < 8; k4++){
                float4 b = *reinterpret_cast<const float4*>(&sh[n][q * 32 + k4 * 4]);
                a = fmaf(b.x, wreg[k4*4],   a);
                a = fmaf(b.y, wreg[k4*4+1], a);
                a = fmaf(b.z, wreg[k4*4+2], a);
                a = fmaf(b.w, wreg[k4*4+3], a);
            }
            acc[m] = a;
        }
    }
    #pragma unroll
    for (int m = 0; m < 16; m++){
        int n = 2 * m + g;
        if (n < nn){
            so[n][c] = acc[m];
            g_xw2h[(n0 + n) * F2 + c] = __float2half_rn(acc[m]);
        }
    }
    __syncthreads();

    int wid = t >> 5, lane = t & 31;
    float2 av = *reinterpret_cast<const float2*>(as2 + lane * 2);
    float2 dv = *reinterpret_cast<const float2*>(ad2 + lane * 2);
    int nend = min(wid * 8 + 8, nn);
    for (int n = wid * 8; n < nend; n++){
        float2 v = *reinterpret_cast<const float2*>(&so[n][lane * 2]);
        float vs = v.x * av.x + v.y * av.y;
        float vd = v.x * dv.x + v.y * dv.y;
        #pragma unroll
        for (int off = 16; off; off >>= 1){
            vs += __shfl_xor_sync(0xffffffffu, vs, off);
            vd += __shfl_xor_sync(0xffffffffu, vd, off);
        }
        if (lane == 0){ g_al2s[n0 + n] = vs; g_al2d[n0 + n] = vd; }
    }
}

// ---------------- layer2 aggregation: smem-staged cooperative weights ----------------
__global__ void kagg2(float* __restrict__ out, const float* __restrict__ b2){
    __shared__ float swt[8][16];                   // per-warp: 16 edge weights
    int wid  = threadIdx.x >> 5;
    int lane = threadIdx.x & 31;
    int w    = blockIdx.x * 8 + wid;
    if (w >= NN) return;
    int beg = g_off[w], end = g_off[w + 1];
    float ald = g_al2d[w];
    const __half2* xwc = reinterpret_cast<const __half2*>(g_xw2h) + lane;
    const int ROW2 = F2 / 2;

    float den = 0.f, a0 = 0.f, a1 = 0.f;
    int j = beg;
    for (; j + 16 <= end; j += 16){
        if (lane < 16){
            int myidx = g_esrc[j + lane];
            swt[wid][lane] = __expf(lrelu(g_al2s[myidx] + ald));
        }
        __syncwarp();
        #pragma unroll
        for (int k = 0; k < 16; k++){
            int   s  = g_esrc[j + k];
            float wk = swt[wid][k];
            float2 v = __half22float2(xwc[s * ROW2]);
            den += wk;
            a0 = fmaf(v.x, wk, a0); a1 = fmaf(v.y, wk, a1);
        }
        __syncwarp();
    }
    for (; j < end; j++){
        int   s  = g_esrc[j];
        float ww = __expf(lrelu(g_al2s[s] + ald));
        float2 v = __half22float2(xwc[s * ROW2]);
        den += ww;
        a0 = fmaf(v.x, ww, a0); a1 = fmaf(v.y, ww, a1);
    }
    float r = 1.f / den;
    *reinterpret_cast<float2*>(out + w * F2 + lane * 2) =
        make_float2(fmaf(a0, r, __ldg(b2 + lane * 2)),
                    fmaf(a1, r, __ldg(b2 + lane * 2 + 1)));
}

extern "C" void kernel_launch(void* const* d_in, const int* in_sizes, int n_in,
                              void* d_out, int out_size){
    const float* x   = (const float*)d_in[0];
    const void*  ei  = d_in[1];
    const float* W1  = (const float*)d_in[2];
    const float* as1 = (const float*)d_in[3];
    const float* ad1 = (const float*)d_in[4];
    const float* b1  = (const float*)d_in[5];
    const float* W2  = (const float*)d_in[6];
    const float* as2 = (const float*)d_in[7];
    const float* ad2 = (const float*)d_in[8];
    const float* b2  = (const float*)d_in[9];
    float* out = (float*)d_out;

    int wb = (NN + 7) / 8;                          // 8 warps per block
    int nb = (NN + 31) / 32;

    kfused<<<EB + NB64, 256>>>(ei, x, W1, as1, ad1);   // histogram+rank | k1
    kscan<<<NBLK, 256>>>();
    kscatter<<<EB, 256>>>(ei);                          // atomic-free, self-cleaning
    kagg1<<<wb, 256>>>();                               // launch #4 → profiled
    k5<<<nb, 128>>>(b1, W2, as2, ad2);
    kagg2<<<wb, 256>>>(out, b2);
}

// round 17
// speedup vs baseline: 1.1378x; 1.0710x over previous
#include <cuda_runtime.h>
#include <cuda_fp16.h>
#include <math_constants.h>

#define NN   50000
#define EE   1600000
#define ETOT 1650000      // EE + NN self loops
#define INCH 34
#define H1   2
#define F1   128          // layer1 concat width
#define F2   64           // layer2 out width
#define NEG  0.2f
#define NBLK ((NN + 255) / 256)     // 196 scan blocks
#define EB   ((ETOT + 255) / 256)   // 6446 edge blocks
#define NB64 ((NN + 63) / 64)       // 782 k1 tile-pair blocks
#define CHUNK 128                    // kagg1 staging chunk (edges)

struct __align__(8) half4 { __half2 lo, hi; };

// ---- scratch (static device globals; zero-initialized at load; self-cleaning) ----
__device__ __half g_xw1h[NN * F1];   // x @ W1 (fp16 storage)      [N,128]
__device__ __half g_xw2h[NN * F2];   // relu(h+b1) @ W2 (fp16)     [N,64]
__device__ float  g_hacc[NN * F1];   // layer1 aggregation (fp32)  [N,128]
__device__ float  g_al1s[NN * H1];
__device__ float  g_al1d[NN * H1];
__device__ float  g_al2s[NN];
__device__ float  g_al2d[NN];
__device__ int    g_cnt [NN];        // dst histogram (zeroed by kscatter for next call)
__device__ int    g_off [NN + 1];    // CSR offsets
__device__ unsigned int g_desc[NBLK];// lookback descriptors (zeroed by kscatter)
__device__ int    g_rank[ETOT];      // rank of edge within its dst bucket
__device__ int    g_esrc[ETOT];      // src index per edge, bucketed by dst

__device__ __forceinline__ float lrelu(float v){ return v >= 0.f ? v : NEG * v; }

// per-block dtype probe: node ids < NN as int64 iff buffer is int64
__device__ __forceinline__ bool detect_is64(const void* __restrict__ ei, int* sflag){
    if (threadIdx.x < 32){
        const long long* p = (const long long*)ei;
        int lane = threadIdx.x;
        bool bad = (p[lane] < 0) || (p[lane] >= NN) ||
                   (p[lane + 32] < 0) || (p[lane + 32] >= NN);
        unsigned anybad = __ballot_sync(0xffffffffu, bad);
        if (lane == 0) *sflag = anybad ? 0 : 1;
    }
    __syncthreads();
    return *sflag != 0;
}

__device__ __forceinline__ void edge_sd(const void* __restrict__ ei, bool is64,
                                        int e, int& s, int& d){
    if (e < EE){
        if (is64){
            const long long* p = (const long long*)ei;
            s = (int)p[e]; d = (int)p[EE + e];
        } else {
            const int* p = (const int*)ei;
            s = p[e]; d = p[EE + e];
        }
    } else {
        s = e - EE; d = s;
    }
}

// ---------------- fused: histogram+rank (blocks 0..EB) | k1 projection+logits (rest) ----------------
__global__ void kfused(const void* __restrict__ ei,
                       const float* __restrict__ x, const float* __restrict__ W1,
                       const float* __restrict__ as1, const float* __restrict__ ad1){
    __shared__ float sx[2][32][36];
    __shared__ float sxw[2][32][F1];
    __shared__ int   sflag;
    int bid = blockIdx.x;

    if (bid < EB){                                  // -------- histogram + rank --------
        bool is64 = detect_is64(ei, &sflag);
        int e = bid * 256 + threadIdx.x;
        if (e < ETOT){
            int s, d; edge_sd(ei, is64, e, s, d);
            g_rank[e] = atomicAdd(&g_cnt[d], 1);
        }
        return;
    }

    // ---------------- k1: two 32-node tiles per block ----------------
    int bk  = bid - EB;
    int sub = threadIdx.x >> 7;                     // 0 or 1: which tile
    int t   = threadIdx.x & 127;                    // channel within tile
    int n0  = bk * 64 + sub * 32;
    int nn  = NN - n0; nn = nn < 0 ? 0 : (nn > 32 ? 32 : nn);
    float (*px)[36] = sx[sub];
    float (*pw)[F1] = sxw[sub];

    int tot = nn * INCH;
    for (int i = t; i < tot; i += 128){
        int r = i / INCH, c = i - r * INCH;
        px[r][c] = x[n0 * INCH + i];
    }
    if (t < 32){ px[t][34] = 0.f; px[t][35] = 0.f; }

    float w[36];
    #pragma unroll
    for (int k = 0; k < INCH; k++) w[k] = W1[k * F1 + t];
    w[34] = 0.f; w[35] = 0.f;
    __syncthreads();

    int n = 0;
    for (; n + 2 <= nn; n += 2){                    // 2-node unroll
        float a0 = 0.f, a1 = 0.f, c0 = 0.f, c1 = 0.f;
        #pragma unroll
        for (int k4 = 0; k4 < 9; k4++){
            float4 b = *reinterpret_cast<const float4*>(&px[n][k4 * 4]);
            float4 d = *reinterpret_cast<const float4*>(&px[n + 1][k4 * 4]);
            a0 = fmaf(b.x, w[k4*4],   a0);
            a1 = fmaf(b.y, w[k4*4+1], a1);
            a0 = fmaf(b.z, w[k4*4+2], a0);
            a1 = fmaf(b.w, w[k4*4+3], a1);
            c0 = fmaf(d.x, w[k4*4],   c0);
            c1 = fmaf(d.y, w[k4*4+1], c1);
            c0 = fmaf(d.z, w[k4*4+2], c0);
            c1 = fmaf(d.w, w[k4*4+3], c1);
        }
        float r0 = a0 + a1, r1 = c0 + c1;
        pw[n][t] = r0;      g_xw1h[(n0 + n) * F1 + t]     = __float2half_rn(r0);
        pw[n + 1][t] = r1;  g_xw1h[(n0 + n + 1) * F1 + t] = __float2half_rn(r1);
    }
    for (; n < nn; n++){
        float a0 = 0.f, a1 = 0.f;
        #pragma unroll
        for (int k4 = 0; k4 < 9; k4++){
            float4 b = *reinterpret_cast<const float4*>(&px[n][k4 * 4]);
            a0 = fmaf(b.x, w[k4*4],   a0);
            a1 = fmaf(b.y, w[k4*4+1], a1);
            a0 = fmaf(b.z, w[k4*4+2], a0);
            a1 = fmaf(b.w, w[k4*4+3], a1);
        }
        float acc = a0 + a1;
        pw[n][t] = acc;
        g_xw1h[(n0 + n) * F1 + t] = __float2half_rn(acc);
    }
    __syncthreads();

    // fused logits: each of 4 warps (per tile) reduces 8 nodes
    int wid = t >> 5, lane = t & 31, h = lane >> 4;
    float4 av = *reinterpret_cast<const float4*>(as1 + lane * 4);
    float4 dv = *reinterpret_cast<const float4*>(ad1 + lane * 4);
    int nend = wid * 8 + 8; if (nend > nn) nend = nn;
    for (int m = wid * 8; m < nend; m++){
        float4 v = *reinterpret_cast<const float4*>(&pw[m][lane * 4]);
        float vs = v.x * av.x + v.y * av.y + v.z * av.z + v.w * av.w;
        float vd = v.x * dv.x + v.y * dv.y + v.z * dv.z + v.w * dv.w;
        #pragma unroll
        for (int off = 8; off; off >>= 1){
            vs += __shfl_xor_sync(0xffffffffu, vs, off);
            vd += __shfl_xor_sync(0xffffffffu, vd, off);
        }
        if ((lane & 15) == 0){
            g_al1s[(n0 + m) * 2 + h] = vs;
            g_al1d[(n0 + m) * 2 + h] = vd;
        }
    }
}

// ---------------- single-pass decoupled-lookback scan ----------------
__global__ void kscan(){
    __shared__ int s[256];
    __shared__ int sbase;
    int b = blockIdx.x, t = threadIdx.x;
    int idx = b * 256 + t;
    int v = (idx < NN) ? g_cnt[idx] : 0;
    s[t] = v;
    __syncthreads();
    #pragma unroll
    for (int off = 1; off < 256; off <<= 1){
        int u = (t >= off) ? s[t - off] : 0;
        __syncthreads();
        s[t] += u;
        __syncthreads();
    }
    int incl = s[t];
    int agg  = s[255];
    if (t == 0){
        if (b == 0){
            sbase = 0;
            atomicExch(&g_desc[0], 0x80000000u | (unsigned)agg);   // PREFIX
        } else {
            atomicExch(&g_desc[b], 0x40000000u | (unsigned)agg);   // AGGREGATE
            int sum = 0;
            for (int p = b - 1; p >= 0; ){
                unsigned d;
                do { d = atomicAdd(&g_desc[p], 0u); } while (d == 0u);
                sum += (int)(d & 0x3FFFFFFFu);
                if (d & 0x80000000u) break;
                p--;
            }
            sbase = sum;
            atomicExch(&g_desc[b], 0x80000000u | (unsigned)(sum + agg));
        }
    }
    __syncthreads();
    if (idx < NN) g_off[idx] = sbase + incl - v;
    if (b == NBLK - 1 && t == 255) g_off[NN] = ETOT;
}

// ---------------- scatter (atomic-free) + state cleanup for next call ----------------
__global__ void kscatter(const void* __restrict__ ei){
    __shared__ int sflag;
    bool is64 = detect_is64(ei, &sflag);
    int e = blockIdx.x * blockDim.x + threadIdx.x;
    if (e < ETOT){
        int s, d; edge_sd(ei, is64, e, s, d);
        g_esrc[g_off[d] + g_rank[e]] = s;
    }
    if (e < NN)   g_cnt[e]  = 0;      // ready for next call
    if (e < NBLK) g_desc[e] = 0u;
}

// ---------------- layer1 aggregation: two-phase staged (128-edge chunks) ----------------
__global__ void kagg1(){
    __shared__ float swt[8][2 * CHUNK];            // per-warp: CHUNK edges x 2 heads (8 KB)
    int wid  = threadIdx.x >> 5;
    int lane = threadIdx.x & 31;
    int w    = blockIdx.x * 8 + wid;
    if (w >= NN) return;
    int beg = g_off[w], end = g_off[w + 1];
    int h   = lane >> 4;                           // lanes 0-15 head0, 16-31 head1
    float ald0 = g_al1d[w * 2], ald1 = g_al1d[w * 2 + 1];
    const __half* base = g_xw1h + lane * 4;        // lane owns 4 of 128 channels
    float* wt = swt[wid];

    float den = 0.f;
    float a0 = 0.f, a1 = 0.f, a2 = 0.f, a3 = 0.f;
    for (int j = beg; j < end; ){
        int cnt = end - j; if (cnt > CHUNK) cnt = CHUNK;
        // phase 1: lanes cooperatively compute cnt*2 weights (each exactly once)
        for (int q = lane; q < cnt * 2; q += 32){
            int ii = q >> 1, hh = q & 1;
            int s  = g_esrc[j + ii];
            float al = g_al1s[s * 2 + hh] + (hh ? ald1 : ald0);
            wt[q] = __expf(lrelu(al));
        }
        __syncwarp();
        // phase 2: lean accumulate (uniform idx LDG + uniform LDS weight + gather)
        int k = 0;
        for (; k + 4 <= cnt; k += 4){
            int s0 = g_esrc[j+k], s1 = g_esrc[j+k+1], s2 = g_esrc[j+k+2], s3 = g_esrc[j+k+3];
            float w0 = wt[2*k + h],     w1 = wt[2*(k+1) + h];
            float w2 = wt[2*(k+2) + h], w3 = wt[2*(k+3) + h];
            half4 u0 = *reinterpret_cast<const half4*>(base + s0 * F1);
            half4 u1 = *reinterpret_cast<const half4*>(base + s1 * F1);
            half4 u2 = *reinterpret_cast<const half4*>(base + s2 * F1);
            half4 u3 = *reinterpret_cast<const half4*>(base + s3 * F1);
            den += (w0 + w1) + (w2 + w3);
            float2 p, q2;
            p = __half22float2(u0.lo); q2 = __half22float2(u0.hi);
            a0 = fmaf(p.x, w0, a0); a1 = fmaf(p.y, w0, a1); a2 = fmaf(q2.x, w0, a2); a3 = fmaf(q2.y, w0, a3);
            p = __half22float2(u1.lo); q2 = __half22float2(u1.hi);
            a0 = fmaf(p.x, w1, a0); a1 = fmaf(p.y, w1, a1); a2 = fmaf(q2.x, w1, a2); a3 = fmaf(q2.y, w1, a3);
            p = __half22float2(u2.lo); q2 = __half22float2(u2.hi);
            a0 = fmaf(p.x, w2, a0); a1 = fmaf(p.y, w2, a1); a2 = fmaf(q2.x, w2, a2); a3 = fmaf(q2.y, w2, a3);
            p = __half22float2(u3.lo); q2 = __half22float2(u3.hi);
            a0 = fmaf(p.x, w3, a0); a1 = fmaf(p.y, w3, a1); a2 = fmaf(q2.x, w3, a2); a3 = fmaf(q2.y, w3, a3);
        }
        for (; k < cnt; k++){
            int   s  = g_esrc[j + k];
            float ww = wt[2*k + h];
            half4 u  = *reinterpret_cast<const half4*>(base + s * F1);
            float2 p = __half22float2(u.lo), q2 = __half22float2(u.hi);
            den += ww;
            a0 = fmaf(p.x, ww, a0); a1 = fmaf(p.y, ww, a1);
            a2 = fmaf(q2.x, ww, a2); a3 = fmaf(q2.y, ww, a3);
        }
        __syncwarp();
        j += cnt;
    }
    float r = 1.f / den;
    *reinterpret_cast<float4*>(g_hacc + w * F1 + lane * 4) =
        make_float4(a0 * r, a1 * r, a2 * r, a3 * r);
}

// ---------------- layer2 projection + fused logits ----------------
__global__ void k5(const float* __restrict__ b1, const float* __restrict__ W2,
                   const float* __restrict__ as2, const float* __restrict__ ad2){
    __shared__ float sh[32][F1];                   // 16 KB
    __shared__ float so[32][F2];                   // 8 KB
    int n0 = blockIdx.x * 32;
    int t  = threadIdx.x;                          // 128 threads
    int nn = min(32, NN - n0);

    float bb = b1[t];
    for (int r = 0; r < nn; r++)
        sh[r][t] = fmaxf(g_hacc[(n0 + r) * F1 + t] + bb, 0.f);
    __syncthreads();

    int c = t & 63, g = t >> 6;                    // channel, node-parity
    float acc[16];
    #pragma unroll
    for (int m = 0; m < 16; m++) acc[m] = 0.f;

    #pragma unroll
    for (int q = 0; q < 4; q++){
        float wreg[32];
        #pragma unroll
        for (int kk = 0; kk < 32; kk++) wreg[kk] = W2[(q * 32 + kk) * F2 + c];
        #pragma unroll 4
        for (int m = 0; m < 16; m++){
            int n = 2 * m + g;
            float a = acc[m];
            #pragma unroll
            for (int k4 = 0; k4 < 8; k4++){
                float4 b = *reinterpret_cast<const float4*>(&sh[n][q * 32 + k4 * 4]);
                a = fmaf(b.x, wreg[k4*4],   a);
                a = fmaf(b.y, wreg[k4*4+1], a);
                a = fmaf(b.z, wreg[k4*4+2], a);
                a = fmaf(b.w, wreg[k4*4+3], a);
            }
            acc[m] = a;
        }
    }
    #pragma unroll
    for (int m = 0; m < 16; m++){
        int n = 2 * m + g;
        if (n < nn){
            so[n][c] = acc[m];
            g_xw2h[(n0 + n) * F2 + c] = __float2half_rn(acc[m]);
        }
    }
    __syncthreads();

    int wid = t >> 5, lane = t & 31;
    float2 av = *reinterpret_cast<const float2*>(as2 + lane * 2);
    float2 dv = *reinterpret_cast<const float2*>(ad2 + lane * 2);
    int nend = min(wid * 8 + 8, nn);
    for (int n = wid * 8; n < nend; n++){
        float2 v = *reinterpret_cast<const float2*>(&so[n][lane * 2]);
        float vs = v.x * av.x + v.y * av.y;
        float vd = v.x * dv.x + v.y * dv.y;
        #pragma unroll
        for (int off = 16; off; off >>= 1){
            vs += __shfl_xor_sync(0xffffffffu, vs, off);
            vd += __shfl_xor_sync(0xffffffffu, vd, off);
        }
        if (lane == 0){ g_al2s[n0 + n] = vs; g_al2d[n0 + n] = vd; }
    }
}

// ---------------- layer2 aggregation: smem-staged cooperative weights ----------------
__global__ void kagg2(float* __restrict__ out, const float* __restrict__ b2){
    __shared__ float swt[8][16];                   // per-warp: 16 edge weights
    int wid  = threadIdx.x >> 5;
    int lane = threadIdx.x & 31;
    int w    = blockIdx.x * 8 + wid;
    if (w >= NN) return;
    int beg = g_off[w], end = g_off[w + 1];
    float ald = g_al2d[w];
    const __half2* xwc = reinterpret_cast<const __half2*>(g_xw2h) + lane;
    const int ROW2 = F2 / 2;

    float den = 0.f, a0 = 0.f, a1 = 0.f;
    int j = beg;
    for (; j + 16 <= end; j += 16){
        if (lane < 16){
            int myidx = g_esrc[j + lane];
            swt[wid][lane] = __expf(lrelu(g_al2s[myidx] + ald));
        }
        __syncwarp();
        #pragma unroll
        for (int k = 0; k < 16; k++){
            int   s  = g_esrc[j + k];
            float wk = swt[wid][k];
            float2 v = __half22float2(xwc[s * ROW2]);
            den += wk;
            a0 = fmaf(v.x, wk, a0); a1 = fmaf(v.y, wk, a1);
        }
        __syncwarp();
    }
    for (; j < end; j++){
        int   s  = g_esrc[j];
        float ww = __expf(lrelu(g_al2s[s] + ald));
        float2 v = __half22float2(xwc[s * ROW2]);
        den += ww;
        a0 = fmaf(v.x, ww, a0); a1 = fmaf(v.y, ww, a1);
    }
    float r = 1.f / den;
    *reinterpret_cast<float2*>(out + w * F2 + lane * 2) =
        make_float2(fmaf(a0, r, __ldg(b2 + lane * 2)),
                    fmaf(a1, r, __ldg(b2 + lane * 2 + 1)));
}

extern "C" void kernel_launch(void* const* d_in, const int* in_sizes, int n_in,
                              void* d_out, int out_size){
    const float* x   = (const float*)d_in[0];
    const void*  ei  = d_in[1];
    const float* W1  = (const float*)d_in[2];
    const float* as1 = (const float*)d_in[3];
    const float* ad1 = (const float*)d_in[4];
    const float* b1  = (const float*)d_in[5];
    const float* W2  = (const float*)d_in[6];
    const float* as2 = (const float*)d_in[7];
    const float* ad2 = (const float*)d_in[8];
    const float* b2  = (const float*)d_in[9];
    float* out = (float*)d_out;

    int wb = (NN + 7) / 8;                          // 8 warps per block
    int nb = (NN + 31) / 32;

    kfused<<<EB + NB64, 256>>>(ei, x, W1, as1, ad1);   // histogram+rank | k1
    kscan<<<NBLK, 256>>>();
    kscatter<<<EB, 256>>>(ei);                          // atomic-free, self-cleaning
    kagg1<<<wb, 256>>>();                               // launch #4 → profiled
    k5<<<nb, 128>>>(b1, W2, as2, ad2);
    kagg2<<<wb, 256>>>(out, b2);
}